// round 4
// baseline (speedup 1.0000x reference)
#include <cuda_runtime.h>
#include <cstdint>

#define Bz    64
#define Sz    512
#define Hz    1024
#define NINz  128
#define NOUTz 128
#define GRIDz 128
#define NTH   512
#define NPC   8      // neurons per CTA per layer

// Ping-pong hidden-state buffers, [parity][K][batch]. Device globals (no alloc allowed).
__device__ float g_h1[2][Hz][Bz];
__device__ float g_h2[2][Hz][Bz];
__device__ unsigned g_cnt;
__device__ unsigned g_gen;

// ---------------- packed fp32 helpers (fma.rn.f32x2 is PTX-only) ------------
__device__ __forceinline__ void fma2(unsigned long long& a,
                                     unsigned long long w,
                                     unsigned long long h) {
    asm("fma.rn.f32x2 %0, %1, %2, %0;" : "+l"(a) : "l"(w), "l"(h));
}
__device__ __forceinline__ unsigned long long pack2(float v) {
    unsigned long long r;
    asm("mov.b64 %0, {%1, %1};" : "=l"(r) : "f"(v));
    return r;
}

// ---------------- grid barrier (all 128 CTAs co-resident: 1 CTA/SM) ---------
__device__ __forceinline__ void gridbar() {
    __syncthreads();
    if (threadIdx.x == 0) {
        __threadfence();
        unsigned gen = *(volatile unsigned*)&g_gen;
        if (atomicAdd(&g_cnt, 1u) == GRIDz - 1u) {
            g_cnt = 0u;
            __threadfence();
            *(volatile unsigned*)&g_gen = gen + 1u;
        } else {
            while (*(volatile unsigned*)&g_gen == gen) { }
            __threadfence();
        }
    }
    __syncthreads();
}

// SMEM layout (floats):
//   sWtA[1024][16] : slot j<8 -> W_hh0 row (c8+j), j>=8 -> W_ih1 row (c8+j-8)
//   sWtB[1024][8]  : W_hh1 rows
//   sWx [128][8]   : W_ih0 rows
//   sCb [16]       : combined biases
//   sRed[8][8][64] : float2 partial-sum reduction buffer
#define OFF_WTA 0
#define OFF_WTB (Hz * 16)
#define OFF_WX  (OFF_WTB + Hz * 8)
#define OFF_CB  (OFF_WX + NINz * 8)
#define OFF_RED (OFF_CB + 16)
#define SMEM_FLOATS (OFF_RED + 8 * 8 * 64 * 2)
#define SMEM_BYTES  (SMEM_FLOATS * 4)

__global__ __launch_bounds__(NTH, 1)
void rnn_persistent_kernel(const float* __restrict__ x,
                           const float* __restrict__ W_ih0,
                           const float* __restrict__ b_ih0,
                           const float* __restrict__ W_hh0,
                           const float* __restrict__ b_hh0,
                           const float* __restrict__ W_ih1,
                           const float* __restrict__ b_ih1,
                           const float* __restrict__ W_hh1,
                           const float* __restrict__ b_hh1,
                           const float* __restrict__ W_fc,
                           const float* __restrict__ b_fc,
                           float* __restrict__ out) {
    extern __shared__ float sm[];
    float* sWtA = sm + OFF_WTA;
    float* sWtB = sm + OFF_WTB;
    float* sWx  = sm + OFF_WX;
    float* sCb  = sm + OFF_CB;
    float2* sRed = (float2*)(sm + OFF_RED);

    const int c   = blockIdx.x;
    const int tid = threadIdx.x;
    const int c8  = c * NPC;

    // ---------------- load weight slices (once) ----------------
    #pragma unroll 1
    for (int j = 0; j < 16; ++j) {
        const float* src = (j < 8) ? (W_hh0 + (c8 + j) * Hz)
                                   : (W_ih1 + (c8 + j - 8) * Hz);
        for (int K = tid; K < Hz; K += NTH) sWtA[K * 16 + j] = src[K];
    }
    #pragma unroll 1
    for (int j = 0; j < 8; ++j) {
        const float* src = W_hh1 + (c8 + j) * Hz;
        for (int K = tid; K < Hz; K += NTH) sWtB[K * 8 + j] = src[K];
    }
    #pragma unroll 1
    for (int j = 0; j < 8; ++j) {
        const float* src = W_ih0 + (c8 + j) * NINz;
        for (int K = tid; K < NINz; K += NTH) sWx[K * 8 + j] = src[K];
    }
    if (tid < 16) {
        sCb[tid] = (tid < 8) ? (b_ih0[c8 + tid] + b_hh0[c8 + tid])
                             : (b_ih1[c8 + tid - 8] + b_hh1[c8 + tid - 8]);
    }
    // zero the "t = -1" slots this CTA owns (buffers hold junk across graph replays)
    {
        int r = tid >> 6;        // 0..7
        int b = tid & 63;
        g_h1[1][c8 + r][b] = 0.f;
        g_h2[1][c8 + r][b] = 0.f;
    }
    __syncthreads();
    gridbar();

    const int b  = tid & 63;     // batch lane
    const int Kc = tid >> 6;     // K-slice 0..7
    const int K0 = Kc << 7;      // * 128

    // ---------------- pipelined recurrence: phase p does L1[p] and L2[p-1] ---
    for (int p = 0; p <= Sz; ++p) {
        unsigned long long acc[8] = {0ull,0ull,0ull,0ull,0ull,0ull,0ull,0ull};

        // Prefetch x[:, p, :] early so the LDG.128 latency overlaps Part A FMAs.
        float4 xv0, xv1, xv2, xv3;
        if (p < Sz) {
            const float4* xp = (const float4*)(x + (size_t)b * (Sz * NINz)
                                                 + (size_t)p * NINz + Kc * 16);
            xv0 = __ldg(xp + 0); xv1 = __ldg(xp + 1);
            xv2 = __ldg(xp + 2); xv3 = __ldg(xp + 3);
        }

        // Part A: h1[p-1] x (W_hh0 | W_ih1)  -> all 8 neuron-pair accs
        {
            const float* hp = &g_h1[(p + 1) & 1][0][0] + b;
            #pragma unroll 4
            for (int K = K0; K < K0 + 128; ++K) {
                float hv = __ldcg(hp + K * Bz);
                unsigned long long hh = pack2(hv);
                const ulonglong2* w = (const ulonglong2*)(sWtA + K * 16);
                ulonglong2 w0 = w[0], w1 = w[1], w2 = w[2], w3 = w[3];
                fma2(acc[0], w0.x, hh); fma2(acc[1], w0.y, hh);
                fma2(acc[2], w1.x, hh); fma2(acc[3], w1.y, hh);
                fma2(acc[4], w2.x, hh); fma2(acc[5], w2.y, hh);
                fma2(acc[6], w3.x, hh); fma2(acc[7], w3.y, hh);
            }
        }
        // Part B1: h2[p-2] x W_hh1  -> L2 accs (4..7)
        if (p >= 1) {
            const float* hp = &g_h2[p & 1][0][0] + b;
            #pragma unroll 4
            for (int K = K0; K < K0 + 128; ++K) {
                float hv = __ldcg(hp + K * Bz);
                unsigned long long hh = pack2(hv);
                const ulonglong2* w = (const ulonglong2*)(sWtB + K * 8);
                ulonglong2 w0 = w[0], w1 = w[1];
                fma2(acc[4], w0.x, hh); fma2(acc[5], w0.y, hh);
                fma2(acc[6], w1.x, hh); fma2(acc[7], w1.y, hh);
            }
        }
        // Part B2: x[:, p, :] x W_ih0 -> L1 accs (0..3); thread's i-slice = Kc*16..+16
        if (p < Sz) {
            float vals[16] = { xv0.x, xv0.y, xv0.z, xv0.w,
                               xv1.x, xv1.y, xv1.z, xv1.w,
                               xv2.x, xv2.y, xv2.z, xv2.w,
                               xv3.x, xv3.y, xv3.z, xv3.w };
            #pragma unroll
            for (int r = 0; r < 16; ++r) {
                int i = Kc * 16 + r;
                unsigned long long hh = pack2(vals[r]);
                const ulonglong2* w = (const ulonglong2*)(sWx + i * 8);
                ulonglong2 w0 = w[0], w1 = w[1];
                fma2(acc[0], w0.x, hh); fma2(acc[1], w0.y, hh);
                fma2(acc[2], w1.x, hh); fma2(acc[3], w1.y, hh);
            }
        }

        // -------- cross-Kc reduction in SMEM, then tanh + publish ----------
        #pragma unroll
        for (int j = 0; j < 8; ++j)
            ((unsigned long long*)sRed)[j * 512 + Kc * 64 + b] = acc[j];
        __syncthreads();
        {
            int jj = tid >> 6;   // neuron-pair slot 0..7
            int b2 = tid & 63;
            float sx = 0.f, sy = 0.f;
            #pragma unroll
            for (int q = 0; q < 8; ++q) {
                float2 v = sRed[jj * 512 + q * 64 + b2];
                sx += v.x; sy += v.y;
            }
            sx += sCb[2 * jj];     sy += sCb[2 * jj + 1];
            sx = tanhf(sx);        sy = tanhf(sy);
            if (jj < 4) {          // layer-1 neurons
                if (p < Sz) {
                    int row = c8 + 2 * jj;
                    __stcg(&g_h1[p & 1][row][b2], sx);
                    __stcg(&g_h1[p & 1][row + 1][b2], sy);
                }
            } else {               // layer-2 neurons
                if (p >= 1) {
                    int row = c8 + 2 * (jj - 4);
                    __stcg(&g_h2[(p + 1) & 1][row][b2], sx);
                    __stcg(&g_h2[(p + 1) & 1][row + 1][b2], sy);
                }
            }
        }
        gridbar();   // includes __syncthreads: also protects sRed reuse
    }

    // ---------------- FC head: out[b][o] = h2[511] . W_fc[o] + b_fc[o] ------
    {
        const float* hL = &g_h2[1][0][0];     // h2[511] lives in parity 1
        int P  = c * 64 + (tid >> 3);         // output id 0..8191
        int kc = tid & 7;                     // 8-way K split
        int bb = P >> 7;
        int oo = P & 127;
        const float4* wf = (const float4*)(W_fc + oo * Hz + kc * 128);
        float s = 0.f;
        #pragma unroll 4
        for (int q = 0; q < 32; ++q) {
            float4 w4 = __ldg(wf + q);
            int k = kc * 128 + q * 4;
            s += __ldcg(hL + (k + 0) * Bz + bb) * w4.x;
            s += __ldcg(hL + (k + 1) * Bz + bb) * w4.y;
            s += __ldcg(hL + (k + 2) * Bz + bb) * w4.z;
            s += __ldcg(hL + (k + 3) * Bz + bb) * w4.w;
        }
        s += __shfl_down_sync(0xffffffffu, s, 4, 8);
        s += __shfl_down_sync(0xffffffffu, s, 2, 8);
        s += __shfl_down_sync(0xffffffffu, s, 1, 8);
        if (kc == 0) out[P] = s + b_fc[oo];
    }
}

extern "C" void kernel_launch(void* const* d_in, const int* in_sizes, int n_in,
                              void* d_out, int out_size) {
    const float* x     = (const float*)d_in[0];
    const float* W_ih0 = (const float*)d_in[1];
    const float* b_ih0 = (const float*)d_in[2];
    const float* W_hh0 = (const float*)d_in[3];
    const float* b_hh0 = (const float*)d_in[4];
    const float* W_ih1 = (const float*)d_in[5];
    const float* b_ih1 = (const float*)d_in[6];
    const float* W_hh1 = (const float*)d_in[7];
    const float* b_hh1 = (const float*)d_in[8];
    const float* W_fc  = (const float*)d_in[9];
    const float* b_fc  = (const float*)d_in[10];
    float* out = (float*)d_out;

    // >48KB dynamic smem needs the attribute; idempotent and capture-safe
    // (not a stream operation, so it is not recorded into the graph).
    cudaFuncSetAttribute(rnn_persistent_kernel,
                         cudaFuncAttributeMaxDynamicSharedMemorySize, SMEM_BYTES);

    rnn_persistent_kernel<<<GRIDz, NTH, SMEM_BYTES>>>(
        x, W_ih0, b_ih0, W_hh0, b_hh0,
        W_ih1, b_ih1, W_hh1, b_hh1, W_fc, b_fc, out);
}

// round 10
// speedup vs baseline: 1.6546x; 1.6546x over previous
#include <cuda_runtime.h>
#include <cstdint>

#define Bz    64
#define Sz    512
#define Hz    1024
#define NINz  128
#define NOUTz 128
#define GRIDz 128
#define NTH   512
#define NPC   8      // neurons per CTA per layer
#define NKC   16     // K-slices per CTA
#define KPT   64     // K per thread (Hz / NKC)

// Ping-pong hidden-state buffers, [parity][K][batch]. Device globals (no alloc allowed).
__device__ float g_h1[2][Hz][Bz];
__device__ float g_h2[2][Hz][Bz];
__device__ unsigned g_cnt;
__device__ unsigned g_gen;

// ---------------- packed fp32 helpers (fma.rn.f32x2 is PTX-only) ------------
__device__ __forceinline__ void fma2(unsigned long long& a,
                                     unsigned long long w,
                                     unsigned long long h) {
    asm("fma.rn.f32x2 %0, %1, %2, %0;" : "+l"(a) : "l"(w), "l"(h));
}
__device__ __forceinline__ unsigned long long pack2(float v) {
    unsigned long long r;
    asm("mov.b64 %0, {%1, %1};" : "=l"(r) : "f"(v));
    return r;
}

// ---------------- grid barrier (all 128 CTAs co-resident: 1 CTA/SM) ---------
__device__ __forceinline__ void gridbar() {
    __syncthreads();
    if (threadIdx.x == 0) {
        __threadfence();
        unsigned gen = *(volatile unsigned*)&g_gen;
        if (atomicAdd(&g_cnt, 1u) == GRIDz - 1u) {
            g_cnt = 0u;
            __threadfence();
            *(volatile unsigned*)&g_gen = gen + 1u;
        } else {
            while (*(volatile unsigned*)&g_gen == gen) { }
            __threadfence();
        }
    }
    __syncthreads();
}

// SMEM layout (floats):
//   sWtA[1024][16] : slot j<8 -> W_hh0 row (c8+j), j>=8 -> W_ih1 row (c8+j-8)
//   sWtB[1024][8]  : W_hh1 rows
//   sWx [128][8]   : W_ih0 rows
//   sCb [16]       : combined biases
//   sRed[8][16][32] float4 : partial sums; float4 = {b0:(n2j,n2j+1), b1:(n2j,n2j+1)}
#define OFF_WTA 0
#define OFF_WTB (Hz * 16)
#define OFF_WX  (OFF_WTB + Hz * 8)
#define OFF_CB  (OFF_WX + NINz * 8)
#define OFF_RED (OFF_CB + 16)
#define SMEM_FLOATS (OFF_RED + 8 * NKC * 32 * 4)
#define SMEM_BYTES  (SMEM_FLOATS * 4)

__global__ __launch_bounds__(NTH, 1)
void rnn_persistent_kernel(const float* __restrict__ x,
                           const float* __restrict__ W_ih0,
                           const float* __restrict__ b_ih0,
                           const float* __restrict__ W_hh0,
                           const float* __restrict__ b_hh0,
                           const float* __restrict__ W_ih1,
                           const float* __restrict__ b_ih1,
                           const float* __restrict__ W_hh1,
                           const float* __restrict__ b_hh1,
                           const float* __restrict__ W_fc,
                           const float* __restrict__ b_fc,
                           float* __restrict__ out) {
    extern __shared__ float sm[];
    float*  sWtA = sm + OFF_WTA;
    float*  sWtB = sm + OFF_WTB;
    float*  sWx  = sm + OFF_WX;
    float*  sCb  = sm + OFF_CB;
    float4* sRed = (float4*)(sm + OFF_RED);

    const int c   = blockIdx.x;
    const int tid = threadIdx.x;
    const int c8  = c * NPC;

    // ---------------- load weight slices (once) ----------------
    #pragma unroll 1
    for (int j = 0; j < 16; ++j) {
        const float* src = (j < 8) ? (W_hh0 + (c8 + j) * Hz)
                                   : (W_ih1 + (c8 + j - 8) * Hz);
        for (int K = tid; K < Hz; K += NTH) sWtA[K * 16 + j] = src[K];
    }
    #pragma unroll 1
    for (int j = 0; j < 8; ++j) {
        const float* src = W_hh1 + (c8 + j) * Hz;
        for (int K = tid; K < Hz; K += NTH) sWtB[K * 8 + j] = src[K];
    }
    #pragma unroll 1
    for (int j = 0; j < 8; ++j) {
        const float* src = W_ih0 + (c8 + j) * NINz;
        for (int K = tid; K < NINz; K += NTH) sWx[K * 8 + j] = src[K];
    }
    if (tid < 16) {
        sCb[tid] = (tid < 8) ? (b_ih0[c8 + tid] + b_hh0[c8 + tid])
                             : (b_ih1[c8 + tid - 8] + b_hh1[c8 + tid - 8]);
    }
    // zero the "t = -1" slots this CTA owns (buffers hold junk across graph
    // replays). g_h2[0] too: phase 0's merged loop reads it (contributes 0).
    {
        int r = tid >> 6;        // 0..7
        int b = tid & 63;
        g_h1[1][c8 + r][b] = 0.f;
        g_h2[1][c8 + r][b] = 0.f;
        g_h2[0][c8 + r][b] = 0.f;
    }
    __syncthreads();
    gridbar();

    const int lane = tid & 31;     // batch pair lane: handles b0=2*lane, b1=2*lane+1
    const int Kc   = tid >> 5;     // K-slice 0..15
    const int K0   = Kc * KPT;

    // ---------------- pipelined recurrence: phase p does L1[p] and L2[p-1] ---
    for (int p = 0; p <= Sz; ++p) {
        // acc[u][j]: u=0 -> batch b0, u=1 -> b1; j = neuron pair 0..7
        // pairs 0..3 = layer-1 neurons, pairs 4..7 = layer-2 neurons
        unsigned long long a0[8] = {0,0,0,0,0,0,0,0};
        unsigned long long a1[8] = {0,0,0,0,0,0,0,0};

        // Prefetch x rows early (8 i-values x 2 batches); overlaps the K loop.
        float4 xva0, xva1, xvb0, xvb1;
        if (p < Sz) {
            const float* xa = x + (size_t)(2 * lane) * (Sz * NINz)
                                + (size_t)p * NINz + Kc * 8;
            const float* xb = xa + (size_t)(Sz * NINz);
            xva0 = __ldg((const float4*)xa);
            xva1 = __ldg((const float4*)(xa + 4));
            xvb0 = __ldg((const float4*)xb);
            xvb1 = __ldg((const float4*)(xb + 4));
        }

        // Merged K loop: h1[p-1] x (W_hh0|W_ih1)  +  h2[p-2] x W_hh1
        {
            const float2* hp1 = (const float2*)(&g_h1[(p + 1) & 1][0][0]) + lane;
            const float2* hp2 = (const float2*)(&g_h2[p & 1][0][0]) + lane;
            #pragma unroll 4
            for (int K = K0; K < K0 + KPT; ++K) {
                float2 h1v = __ldcg(hp1 + K * 32);
                float2 h2v = __ldcg(hp2 + K * 32);
                unsigned long long p10 = pack2(h1v.x), p11 = pack2(h1v.y);
                unsigned long long p20 = pack2(h2v.x), p21 = pack2(h2v.y);

                const ulonglong2* wa = (const ulonglong2*)(sWtA + K * 16);
                ulonglong2 wa0 = wa[0], wa1 = wa[1], wa2 = wa[2], wa3 = wa[3];
                fma2(a0[0], wa0.x, p10); fma2(a1[0], wa0.x, p11);
                fma2(a0[1], wa0.y, p10); fma2(a1[1], wa0.y, p11);
                fma2(a0[2], wa1.x, p10); fma2(a1[2], wa1.x, p11);
                fma2(a0[3], wa1.y, p10); fma2(a1[3], wa1.y, p11);
                fma2(a0[4], wa2.x, p10); fma2(a1[4], wa2.x, p11);
                fma2(a0[5], wa2.y, p10); fma2(a1[5], wa2.y, p11);
                fma2(a0[6], wa3.x, p10); fma2(a1[6], wa3.x, p11);
                fma2(a0[7], wa3.y, p10); fma2(a1[7], wa3.y, p11);

                const ulonglong2* wb = (const ulonglong2*)(sWtB + K * 8);
                ulonglong2 wb0 = wb[0], wb1 = wb[1];
                fma2(a0[4], wb0.x, p20); fma2(a1[4], wb0.x, p21);
                fma2(a0[5], wb0.y, p20); fma2(a1[5], wb0.y, p21);
                fma2(a0[6], wb1.x, p20); fma2(a1[6], wb1.x, p21);
                fma2(a0[7], wb1.y, p20); fma2(a1[7], wb1.y, p21);
            }
        }

        // x part: x[:,p,:] x W_ih0 -> L1 pairs 0..3; i-slice = Kc*8 .. +8
        if (p < Sz) {
            float va[8] = { xva0.x, xva0.y, xva0.z, xva0.w,
                            xva1.x, xva1.y, xva1.z, xva1.w };
            float vb[8] = { xvb0.x, xvb0.y, xvb0.z, xvb0.w,
                            xvb1.x, xvb1.y, xvb1.z, xvb1.w };
            #pragma unroll
            for (int r = 0; r < 8; ++r) {
                int i = Kc * 8 + r;
                unsigned long long pa = pack2(va[r]);
                unsigned long long pb = pack2(vb[r]);
                const ulonglong2* w = (const ulonglong2*)(sWx + i * 8);
                ulonglong2 w0 = w[0], w1 = w[1];
                fma2(a0[0], w0.x, pa); fma2(a1[0], w0.x, pb);
                fma2(a0[1], w0.y, pa); fma2(a1[1], w0.y, pb);
                fma2(a0[2], w1.x, pa); fma2(a1[2], w1.x, pb);
                fma2(a0[3], w1.y, pa); fma2(a1[3], w1.y, pb);
            }
        }

        // -------- cross-Kc reduction in SMEM, then tanh + publish ----------
        #pragma unroll
        for (int j = 0; j < 8; ++j) {
            float2 f0 = *(float2*)&a0[j];
            float2 f1 = *(float2*)&a1[j];
            sRed[(j * NKC + Kc) * 32 + lane] = make_float4(f0.x, f0.y, f1.x, f1.y);
        }
        __syncthreads();
        {
            int jj = tid >> 6;   // neuron-pair slot 0..7
            int b2 = tid & 63;
            const float2* rf = (const float2*)sRed;
            float sx = 0.f, sy = 0.f;
            #pragma unroll
            for (int q = 0; q < NKC; ++q) {
                float2 v = rf[((jj * NKC + q) * 32 + (b2 >> 1)) * 2 + (b2 & 1)];
                sx += v.x; sy += v.y;
            }
            sx += sCb[2 * jj];     sy += sCb[2 * jj + 1];
            sx = tanhf(sx);        sy = tanhf(sy);
            if (jj < 4) {          // layer-1 neurons
                if (p < Sz) {
                    int row = c8 + 2 * jj;
                    __stcg(&g_h1[p & 1][row][b2], sx);
                    __stcg(&g_h1[p & 1][row + 1][b2], sy);
                }
            } else {               // layer-2 neurons
                if (p >= 1) {
                    int row = c8 + 2 * (jj - 4);
                    __stcg(&g_h2[(p + 1) & 1][row][b2], sx);
                    __stcg(&g_h2[(p + 1) & 1][row + 1][b2], sy);
                }
            }
        }
        gridbar();   // includes __syncthreads: also protects sRed reuse
    }

    // ---------------- FC head: out[b][o] = h2[511] . W_fc[o] + b_fc[o] ------
    {
        const float* hL = &g_h2[1][0][0];     // h2[511] lives in parity 1
        int P  = c * 64 + (tid >> 3);         // output id 0..8191
        int kc = tid & 7;                     // 8-way K split
        int bb = P >> 7;
        int oo = P & 127;
        const float4* wf = (const float4*)(W_fc + oo * Hz + kc * 128);
        float s = 0.f;
        #pragma unroll 4
        for (int q = 0; q < 32; ++q) {
            float4 w4 = __ldg(wf + q);
            int k = kc * 128 + q * 4;
            s += __ldcg(hL + (k + 0) * Bz + bb) * w4.x;
            s += __ldcg(hL + (k + 1) * Bz + bb) * w4.y;
            s += __ldcg(hL + (k + 2) * Bz + bb) * w4.z;
            s += __ldcg(hL + (k + 3) * Bz + bb) * w4.w;
        }
        s += __shfl_down_sync(0xffffffffu, s, 4, 8);
        s += __shfl_down_sync(0xffffffffu, s, 2, 8);
        s += __shfl_down_sync(0xffffffffu, s, 1, 8);
        if (kc == 0) out[P] = s + b_fc[oo];
    }
}

extern "C" void kernel_launch(void* const* d_in, const int* in_sizes, int n_in,
                              void* d_out, int out_size) {
    const float* x     = (const float*)d_in[0];
    const float* W_ih0 = (const float*)d_in[1];
    const float* b_ih0 = (const float*)d_in[2];
    const float* W_hh0 = (const float*)d_in[3];
    const float* b_hh0 = (const float*)d_in[4];
    const float* W_ih1 = (const float*)d_in[5];
    const float* b_ih1 = (const float*)d_in[6];
    const float* W_hh1 = (const float*)d_in[7];
    const float* b_hh1 = (const float*)d_in[8];
    const float* W_fc  = (const float*)d_in[9];
    const float* b_fc  = (const float*)d_in[10];
    float* out = (float*)d_out;

    // >48KB dynamic smem needs the attribute; idempotent and capture-safe
    // (not a stream operation, so it is not recorded into the graph).
    cudaFuncSetAttribute(rnn_persistent_kernel,
                         cudaFuncAttributeMaxDynamicSharedMemorySize, SMEM_BYTES);

    rnn_persistent_kernel<<<GRIDz, NTH, SMEM_BYTES>>>(
        x, W_ih0, b_ih0, W_hh0, b_hh0,
        W_ih1, b_ih1, W_hh1, b_hh1, W_fc, b_fc, out);
}